// round 1
// baseline (speedup 1.0000x reference)
#include <cuda_runtime.h>
#include <math.h>

// Problem constants
#define Bb   8
#define Tt   1024
#define DIMf 512
#define Hh   8
#define DKd  64
#define DHh  512
#define NHn  64      // Bb*Hh
#define EPSf 1e-5f

// ---------------- scratch (device globals; no allocation allowed) ----------
__device__ float g_qkv[Bb * 3 * DHh * Tt];     // (b, 1536, t)   48 MB
__device__ float g_ks [NHn * DKd * Tt];        // softmax(k)     16 MB
__device__ float g_ctxp[8 * NHn * DKd * DKd];  // ctx partials    8 MB
__device__ float g_ctx [NHn * DKd * DKd];      // (n, d, e)
__device__ float g_mid [Bb * DHh * Tt];        // content + rel  16 MB
__device__ float g_S   [NHn * Tt];
__device__ float g_P   [DKd * Tt];             // PsumT[d][t]
__device__ float g_bns [DKd * NHn];
__device__ float g_bnq [DKd * NHn];
__device__ float g_sc  [DKd];
__device__ float g_sh  [DKd];

// ---------------- rel-pos band prefix: PsumT[d][t] -------------------------
__global__ void k_prep(const float* __restrict__ relpos) {
    int gid = blockIdx.x * 256 + threadIdx.x;   // 65536 = 64*1024
    int d = gid >> 10, t = gid & 1023;
    int lo = 31 - t;    if (lo < 0)  lo = 0;
    int hi = 1054 - t;  if (hi > 62) hi = 62;
    float s = 0.f;
    for (int ri = lo; ri <= hi; ri++) s += relpos[ri * DKd + d];
    g_P[d * Tt + t] = s;
}

// ---------------- GEMM1: qkv[b,o,t] = sum_f Wqkv[o,f] * x[b,t,f] -----------
// TN gemm: A [1536][512] row-major, B [1024][512] row-major (both K-contig)
__global__ __launch_bounds__(256, 2)
void k_gemm_qkv(const float* __restrict__ W, const float* __restrict__ x) {
    const float* A  = W;
    const float* Bm = x + (long)blockIdx.z * Tt * DIMf;
    float*       C  = g_qkv + (long)blockIdx.z * 1536 * Tt;
    const int K = 512, N = 1024;

    __shared__ float As[16][132];
    __shared__ float Bs[16][132];

    int tid = threadIdx.x;
    int tx = tid & 15, ty = tid >> 4;
    int m0 = blockIdx.y * 128, n0 = blockIdx.x * 128;

    float acc[8][8];
    #pragma unroll
    for (int i = 0; i < 8; i++)
        #pragma unroll
        for (int j = 0; j < 8; j++) acc[i][j] = 0.f;

    int lrow = tid >> 2;
    int lcv  = (tid & 3) * 4;

    for (int k0 = 0; k0 < K; k0 += 16) {
        #pragma unroll
        for (int l = 0; l < 2; l++) {
            int row = lrow + l * 64;
            float4 a = *reinterpret_cast<const float4*>(&A[(long)(m0 + row) * K + k0 + lcv]);
            As[lcv + 0][row] = a.x; As[lcv + 1][row] = a.y;
            As[lcv + 2][row] = a.z; As[lcv + 3][row] = a.w;
            float4 b = *reinterpret_cast<const float4*>(&Bm[(long)(n0 + row) * K + k0 + lcv]);
            Bs[lcv + 0][row] = b.x; Bs[lcv + 1][row] = b.y;
            Bs[lcv + 2][row] = b.z; Bs[lcv + 3][row] = b.w;
        }
        __syncthreads();
        #pragma unroll
        for (int k = 0; k < 16; k++) {
            float a[8], b[8];
            *(float4*)&a[0] = *(const float4*)&As[k][ty * 4];
            *(float4*)&a[4] = *(const float4*)&As[k][64 + ty * 4];
            *(float4*)&b[0] = *(const float4*)&Bs[k][tx * 4];
            *(float4*)&b[4] = *(const float4*)&Bs[k][64 + tx * 4];
            #pragma unroll
            for (int i = 0; i < 8; i++)
                #pragma unroll
                for (int j = 0; j < 8; j++) acc[i][j] += a[i] * b[j];
        }
        __syncthreads();
    }
    #pragma unroll
    for (int i = 0; i < 8; i++) {
        int m = m0 + ((i < 4) ? (ty * 4 + i) : (64 + ty * 4 + i - 4));
        float4 c0 = make_float4(acc[i][0], acc[i][1], acc[i][2], acc[i][3]);
        float4 c1 = make_float4(acc[i][4], acc[i][5], acc[i][6], acc[i][7]);
        *(float4*)&C[(long)m * N + n0 + tx * 4]      = c0;
        *(float4*)&C[(long)m * N + n0 + 64 + tx * 4] = c1;
    }
}

// ---------------- softmax over t for the k slice ---------------------------
__global__ void k_softmax() {
    int row = blockIdx.x;           // 0..4095 == n*64 + d
    int b = row >> 9, r = row & 511;
    const float* src = g_qkv + ((long)b * 1536 + 512 + r) * Tt;
    float*       dst = g_ks  + (long)row * Tt;
    int tid = threadIdx.x;

    float4 x = reinterpret_cast<const float4*>(src)[tid];
    float m = fmaxf(fmaxf(x.x, x.y), fmaxf(x.z, x.w));
    #pragma unroll
    for (int o = 16; o; o >>= 1) m = fmaxf(m, __shfl_xor_sync(0xffffffffu, m, o));
    __shared__ float sm[8];
    __shared__ float ssum[8];
    if ((tid & 31) == 0) sm[tid >> 5] = m;
    __syncthreads();
    float M = sm[0];
    #pragma unroll
    for (int i = 1; i < 8; i++) M = fmaxf(M, sm[i]);

    float e0 = expf(x.x - M), e1 = expf(x.y - M), e2 = expf(x.z - M), e3 = expf(x.w - M);
    float s = e0 + e1 + e2 + e3;
    #pragma unroll
    for (int o = 16; o; o >>= 1) s += __shfl_xor_sync(0xffffffffu, s, o);
    if ((tid & 31) == 0) ssum[tid >> 5] = s;
    __syncthreads();
    float S = 0.f;
    #pragma unroll
    for (int i = 0; i < 8; i++) S += ssum[i];
    float inv = 1.f / S;
    float4 out = make_float4(e0 * inv, e1 * inv, e2 * inv, e3 * inv);
    reinterpret_cast<float4*>(dst)[tid] = out;
}

// ---------------- context partials: ctx[n,d,e] = sum_t ks*v ----------------
__global__ __launch_bounds__(256)
void k_ctx_partial() {
    int n = blockIdx.y, s = blockIdx.x;   // s in 0..7 (t slice of 128)
    int b = n >> 3, h = n & 7;
    const float* Kp = g_ks  + (long)n * DKd * Tt;
    const float* Vp = g_qkv + ((long)b * 1536 + 1024 + h * 64) * Tt;

    __shared__ float Ks[64][68];          // [tt][d]
    __shared__ float Vs[64][68];          // [tt][e]
    int tid = threadIdx.x, tx = tid & 15, ty = tid >> 4;
    float acc[4][4] = {};

    for (int c = 0; c < 2; c++) {
        int t0 = s * 128 + c * 64;
        #pragma unroll
        for (int l = 0; l < 4; l++) {
            int idx = tid + l * 256;
            int d  = idx >> 4;
            int tv = (idx & 15) * 4;
            float4 a = *(const float4*)&Kp[(long)d * Tt + t0 + tv];
            Ks[tv + 0][d] = a.x; Ks[tv + 1][d] = a.y; Ks[tv + 2][d] = a.z; Ks[tv + 3][d] = a.w;
            float4 v = *(const float4*)&Vp[(long)d * Tt + t0 + tv];
            Vs[tv + 0][d] = v.x; Vs[tv + 1][d] = v.y; Vs[tv + 2][d] = v.z; Vs[tv + 3][d] = v.w;
        }
        __syncthreads();
        #pragma unroll 8
        for (int tt = 0; tt < 64; tt++) {
            float a[4], v[4];
            *(float4*)a = *(const float4*)&Ks[tt][ty * 4];
            *(float4*)v = *(const float4*)&Vs[tt][tx * 4];
            #pragma unroll
            for (int i = 0; i < 4; i++)
                #pragma unroll
                for (int j = 0; j < 4; j++) acc[i][j] += a[i] * v[j];
        }
        __syncthreads();
    }
    float* dst = g_ctxp + ((long)s * NHn + n) * 4096;
    #pragma unroll
    for (int i = 0; i < 4; i++) {
        float4 c = make_float4(acc[i][0], acc[i][1], acc[i][2], acc[i][3]);
        *(float4*)&dst[(ty * 4 + i) * 64 + tx * 4] = c;
    }
}

__global__ void k_ctx_reduce() {
    int gid = blockIdx.x * 256 + threadIdx.x;  // 262144
    float s = 0.f;
    #pragma unroll
    for (int p = 0; p < 8; p++) s += g_ctxp[(long)p * 262144 + gid];
    g_ctx[gid] = s;
}

// ---------------- content: mid[n,e,t] = sum_d ctx[n,d,e]*q[n,d,t] ----------
__global__ __launch_bounds__(256)
void k_content() {
    int n = blockIdx.y;
    int t = blockIdx.x * 256 + threadIdx.x;
    int b = n >> 3, h = n & 7;
    const float* Q = g_qkv + ((long)b * 1536 + h * 64) * Tt;

    __shared__ float cs[4096];
    const float4* csrc = (const float4*)(g_ctx + (long)n * 4096);
    for (int i = threadIdx.x; i < 1024; i += 256) ((float4*)cs)[i] = csrc[i];
    __syncthreads();

    float q[64];
    #pragma unroll
    for (int d = 0; d < 64; d++) q[d] = Q[(long)d * Tt + t];

    float* dst = g_mid + ((long)b * 512 + h * 64) * Tt + t;
    #pragma unroll
    for (int e0 = 0; e0 < 64; e0 += 4) {
        float4 a = make_float4(0.f, 0.f, 0.f, 0.f);
        #pragma unroll
        for (int d = 0; d < 64; d++) {
            float4 c = *(const float4*)&cs[d * 64 + e0];
            a.x += c.x * q[d]; a.y += c.y * q[d];
            a.z += c.z * q[d]; a.w += c.w * q[d];
        }
        dst[(long)(e0 + 0) * Tt] = a.x;
        dst[(long)(e0 + 1) * Tt] = a.y;
        dst[(long)(e0 + 2) * Tt] = a.z;
        dst[(long)(e0 + 3) * Tt] = a.w;
    }
}

// ---------------- S[n,t] = sum_d q[n,d,t] * PsumT[d,t] ---------------------
__global__ void k_S() {
    int n = blockIdx.y;
    int t = blockIdx.x * 256 + threadIdx.x;
    int b = n >> 3, h = n & 7;
    const float* Q = g_qkv + ((long)b * 1536 + h * 64) * Tt;
    float s = 0.f;
    #pragma unroll
    for (int d = 0; d < 64; d++) s += Q[(long)d * Tt + t] * g_P[d * Tt + t];
    g_S[n * Tt + t] = s;
}

// ---------------- BN stats partials over rel = v*S -------------------------
__global__ void k_bnstats() {
    int n = blockIdx.y, e = blockIdx.x;
    int b = n >> 3, h = n & 7;
    const float* V  = g_qkv + ((long)b * 1536 + 1024 + h * 64 + e) * Tt;
    const float* Sp = g_S + (long)n * Tt;
    int tid = threadIdx.x;
    float4 v = ((const float4*)V)[tid];
    float4 s = ((const float4*)Sp)[tid];
    float r0 = v.x * s.x, r1 = v.y * s.y, r2 = v.z * s.z, r3 = v.w * s.w;
    float sum = r0 + r1 + r2 + r3;
    float sq  = r0 * r0 + r1 * r1 + r2 * r2 + r3 * r3;
    #pragma unroll
    for (int o = 16; o; o >>= 1) {
        sum += __shfl_xor_sync(0xffffffffu, sum, o);
        sq  += __shfl_xor_sync(0xffffffffu, sq,  o);
    }
    __shared__ float ws[8], wq[8];
    if ((tid & 31) == 0) { ws[tid >> 5] = sum; wq[tid >> 5] = sq; }
    __syncthreads();
    if (tid == 0) {
        float S = 0.f, Q = 0.f;
        #pragma unroll
        for (int i = 0; i < 8; i++) { S += ws[i]; Q += wq[i]; }
        g_bns[e * 64 + n] = S;
        g_bnq[e * 64 + n] = Q;
    }
}

__global__ void k_bnred(const float* __restrict__ gamma, const float* __restrict__ beta) {
    int e = threadIdx.x;  // 64
    float s = 0.f, q = 0.f;
    #pragma unroll
    for (int n = 0; n < 64; n++) { s += g_bns[e * 64 + n]; q += g_bnq[e * 64 + n]; }
    const float cnt = (float)(NHn * Tt);
    float mu  = s / cnt;
    float var = q / cnt - mu * mu;
    float sc  = gamma[e] * rsqrtf(var + EPSf);
    g_sc[e] = sc;
    g_sh[e] = beta[e] - mu * sc;
}

// ---------------- mid += BN(v*S) -------------------------------------------
__global__ void k_reladd() {
    int row = blockIdx.x;             // 0..4095 == b*512 + h*64 + e == n*64+e
    int e = row & 63;
    int n = row >> 6;
    int b = n >> 3, h = n & 7;
    const float* V  = g_qkv + ((long)b * 1536 + 1024 + h * 64 + e) * Tt;
    const float* Sp = g_S + (long)n * Tt;
    float*       D  = g_mid + (long)row * Tt;
    float sc = g_sc[e], sh = g_sh[e];
    int tid = threadIdx.x;
    float4 v = ((const float4*)V)[tid];
    float4 s = ((const float4*)Sp)[tid];
    float4 m = ((const float4*)D)[tid];
    m.x += v.x * s.x * sc + sh;
    m.y += v.y * s.y * sc + sh;
    m.z += v.z * s.z * sc + sh;
    m.w += v.w * s.w * sc + sh;
    ((float4*)D)[tid] = m;
}

// ---------------- GEMM2: out[b,o,t] = sum_d Wout[o,d]*mid[b,d,t] + bout[o] -
// NN gemm: A [512][512] K-contig, B [512][1024] (rows = K, cols contiguous)
__global__ __launch_bounds__(256, 2)
void k_gemm_out(const float* __restrict__ W, const float* __restrict__ bias,
                float* __restrict__ out) {
    const float* A  = W;
    const float* Bm = g_mid + (long)blockIdx.z * 512 * Tt;
    float*       C  = out   + (long)blockIdx.z * 512 * Tt;
    const int K = 512, N = 1024;

    __shared__ float As[16][132];
    __shared__ float Bs[16][132];

    int tid = threadIdx.x;
    int tx = tid & 15, ty = tid >> 4;
    int m0 = blockIdx.y * 128, n0 = blockIdx.x * 128;

    float acc[8][8];
    #pragma unroll
    for (int i = 0; i < 8; i++)
        #pragma unroll
        for (int j = 0; j < 8; j++) acc[i][j] = 0.f;

    int lrow = tid >> 2;
    int lcv  = (tid & 3) * 4;

    for (int k0 = 0; k0 < K; k0 += 16) {
        #pragma unroll
        for (int l = 0; l < 2; l++) {
            int row = lrow + l * 64;
            float4 a = *reinterpret_cast<const float4*>(&A[(long)(m0 + row) * K + k0 + lcv]);
            As[lcv + 0][row] = a.x; As[lcv + 1][row] = a.y;
            As[lcv + 2][row] = a.z; As[lcv + 3][row] = a.w;
            // B direct (rows are K):
            int idx  = tid + l * 256;
            int brow = idx >> 5;
            int bcv  = (idx & 31) * 4;
            float4 b = *reinterpret_cast<const float4*>(&Bm[(long)(k0 + brow) * N + n0 + bcv]);
            *(float4*)&Bs[brow][bcv] = b;
        }
        __syncthreads();
        #pragma unroll
        for (int k = 0; k < 16; k++) {
            float a[8], b[8];
            *(float4*)&a[0] = *(const float4*)&As[k][ty * 4];
            *(float4*)&a[4] = *(const float4*)&As[k][64 + ty * 4];
            *(float4*)&b[0] = *(const float4*)&Bs[k][tx * 4];
            *(float4*)&b[4] = *(const float4*)&Bs[k][64 + tx * 4];
            #pragma unroll
            for (int i = 0; i < 8; i++)
                #pragma unroll
                for (int j = 0; j < 8; j++) acc[i][j] += a[i] * b[j];
        }
        __syncthreads();
    }
    #pragma unroll
    for (int i = 0; i < 8; i++) {
        int m = m0 + ((i < 4) ? (ty * 4 + i) : (64 + ty * 4 + i - 4));
        float bv = bias[m];
        float4 c0 = make_float4(acc[i][0] + bv, acc[i][1] + bv, acc[i][2] + bv, acc[i][3] + bv);
        float4 c1 = make_float4(acc[i][4] + bv, acc[i][5] + bv, acc[i][6] + bv, acc[i][7] + bv);
        *(float4*)&C[(long)m * N + n0 + tx * 4]      = c0;
        *(float4*)&C[(long)m * N + n0 + 64 + tx * 4] = c1;
    }
}

// ---------------- launcher -------------------------------------------------
extern "C" void kernel_launch(void* const* d_in, const int* in_sizes, int n_in,
                              void* d_out, int out_size) {
    const float* x      = (const float*)d_in[0];   // (8,1024,512)
    const float* Wqkv   = (const float*)d_in[1];   // (1536,512)
    const float* Wout   = (const float*)d_in[2];   // (512,512)
    const float* bout   = (const float*)d_in[3];   // (512)
    const float* relpos = (const float*)d_in[4];   // (63,64)
    const float* gamma  = (const float*)d_in[5];   // (64)
    const float* beta   = (const float*)d_in[6];   // (64)
    float* out = (float*)d_out;                    // (8,512,1024)

    k_prep<<<256, 256>>>(relpos);
    k_gemm_qkv<<<dim3(8, 12, 8), 256>>>(Wqkv, x);
    k_softmax<<<4096, 256>>>();
    k_ctx_partial<<<dim3(8, 64), 256>>>();
    k_ctx_reduce<<<1024, 256>>>();
    k_content<<<dim3(4, 64), 256>>>();
    k_S<<<dim3(4, 64), 256>>>();
    k_bnstats<<<dim3(64, 64), 256>>>();
    k_bnred<<<1, 64>>>(gamma, beta);
    k_reladd<<<4096, 256>>>();
    k_gemm_out<<<dim3(8, 4, 8), 256>>>(Wout, bout, out);
}

// round 2
// speedup vs baseline: 2.1082x; 2.1082x over previous
#include <cuda_runtime.h>
#include <math.h>
#include <stdint.h>

// Problem constants
#define Bb   8
#define Tt   1024
#define DIMf 512
#define Hh   8
#define DKd  64
#define DHh  512
#define NHn  64      // Bb*Hh
#define EPSf 1e-5f

// ---------------- scratch (device globals; no allocation allowed) ----------
__device__ float g_qkv[Bb * 3 * DHh * Tt];     // (b, 1536, t)
__device__ float g_ks [NHn * DKd * Tt];        // softmax(k)
__device__ float g_ctxp[8 * NHn * DKd * DKd];  // ctx partials
__device__ float g_ctx [NHn * DKd * DKd];      // (n, d, e)
__device__ float g_mid [Bb * DHh * Tt];        // content + rel
__device__ float g_S   [NHn * Tt];
__device__ float g_P   [DKd * Tt];             // PsumT[d][t]
__device__ float g_bns [DKd * NHn];
__device__ float g_bnq [DKd * NHn];
__device__ float g_sc  [DKd];
__device__ float g_sh  [DKd];

// ---------------- PTX helpers ----------------------------------------------
__device__ __forceinline__ void cp16(void* smem, const void* gmem) {
    uint32_t s = (uint32_t)__cvta_generic_to_shared(smem);
    asm volatile("cp.async.cg.shared.global [%0], [%1], 16;\n" :: "r"(s), "l"(gmem));
}
#define CP_COMMIT() asm volatile("cp.async.commit_group;\n")
#define CP_WAIT0()  asm volatile("cp.async.wait_group 0;\n")
#define CP_WAIT1()  asm volatile("cp.async.wait_group 1;\n")

__device__ __forceinline__ uint32_t f2tf(float x) {
    uint32_t r;
    asm("cvt.rna.tf32.f32 %0, %1;" : "=r"(r) : "f"(x));
    return r;
}

__device__ __forceinline__ void mma_tf32(float* c, const uint32_t* a, const uint32_t* b) {
    asm volatile(
        "mma.sync.aligned.m16n8k8.row.col.f32.tf32.tf32.f32 "
        "{%0,%1,%2,%3}, {%4,%5,%6,%7}, {%8,%9}, {%0,%1,%2,%3};\n"
        : "+f"(c[0]), "+f"(c[1]), "+f"(c[2]), "+f"(c[3])
        : "r"(a[0]), "r"(a[1]), "r"(a[2]), "r"(a[3]), "r"(b[0]), "r"(b[1]));
}

// ---------------- rel-pos band prefix: PsumT[d][t] -------------------------
__global__ void k_prep(const float* __restrict__ relpos) {
    int gid = blockIdx.x * 256 + threadIdx.x;   // 65536 = 64*1024
    int d = gid >> 10, t = gid & 1023;
    int lo = 31 - t;    if (lo < 0)  lo = 0;
    int hi = 1054 - t;  if (hi > 62) hi = 62;
    float s = 0.f;
    for (int ri = lo; ri <= hi; ri++) s += relpos[ri * DKd + d];
    g_P[d * Tt + t] = s;
}

// ===================== GEMM1 (tf32 tensor-core, TN) ========================
// qkv[b,o,t] = sum_f Wqkv[o,f] * x[b,t,f]
// A = Wqkv [1536][512] K-contig, B = x_b [1024][512] K-contig
__global__ __launch_bounds__(256, 2)
void k_gemm_qkv_tc(const float* __restrict__ A, const float* __restrict__ x) {
    const float* Bm = x + (long)blockIdx.z * Tt * DIMf;
    float*       C  = g_qkv + (long)blockIdx.z * 1536 * Tt;
    const int K = 512, N = 1024;

    __shared__ float As[2][128 * 20];
    __shared__ float Bs[2][128 * 20];

    int tid = threadIdx.x;
    int warp = tid >> 5, lane = tid & 31;
    int wm = (warp >> 2) * 64;     // warp M offset (0,64)
    int wn = (warp & 3) * 32;      // warp N offset
    int m0 = blockIdx.y * 128, n0 = blockIdx.x * 128;
    int lrow = lane >> 2, lcol = lane & 3;

    float acc[4][4][4];
    #pragma unroll
    for (int i = 0; i < 4; i++)
        #pragma unroll
        for (int j = 0; j < 4; j++)
            #pragma unroll
            for (int r = 0; r < 4; r++) acc[i][j][r] = 0.f;

    int crow = tid >> 2;          // 0..63
    int ck   = (tid & 3) * 4;

    // prologue: tile 0
    {
        #pragma unroll
        for (int l = 0; l < 2; l++) {
            int row = crow + l * 64;
            cp16(&As[0][row * 20 + ck], &A [(long)(m0 + row) * K + ck]);
            cp16(&Bs[0][row * 20 + ck], &Bm[(long)(n0 + row) * K + ck]);
        }
        CP_COMMIT();
    }

    for (int kt = 0; kt < 32; kt++) {
        int buf = kt & 1;
        if (kt + 1 < 32) {
            int k0 = (kt + 1) * 16;
            #pragma unroll
            for (int l = 0; l < 2; l++) {
                int row = crow + l * 64;
                cp16(&As[buf ^ 1][row * 20 + ck], &A [(long)(m0 + row) * K + k0 + ck]);
                cp16(&Bs[buf ^ 1][row * 20 + ck], &Bm[(long)(n0 + row) * K + k0 + ck]);
            }
            CP_COMMIT();
            CP_WAIT1();
        } else {
            CP_WAIT0();
        }
        __syncthreads();

        #pragma unroll
        for (int ks = 0; ks < 2; ks++) {
            int kb = ks * 8 + lcol;
            uint32_t a[4][4], b[4][2];
            #pragma unroll
            for (int i = 0; i < 4; i++) {
                int m = wm + i * 16 + lrow;
                a[i][0] = f2tf(As[buf][m * 20 + kb]);
                a[i][1] = f2tf(As[buf][(m + 8) * 20 + kb]);
                a[i][2] = f2tf(As[buf][m * 20 + kb + 4]);
                a[i][3] = f2tf(As[buf][(m + 8) * 20 + kb + 4]);
            }
            #pragma unroll
            for (int j = 0; j < 4; j++) {
                int n = wn + j * 8 + lrow;
                b[j][0] = f2tf(Bs[buf][n * 20 + kb]);
                b[j][1] = f2tf(Bs[buf][n * 20 + kb + 4]);
            }
            #pragma unroll
            for (int i = 0; i < 4; i++)
                #pragma unroll
                for (int j = 0; j < 4; j++)
                    mma_tf32(acc[i][j], a[i], b[j]);
        }
        __syncthreads();
    }

    #pragma unroll
    for (int i = 0; i < 4; i++) {
        #pragma unroll
        for (int j = 0; j < 4; j++) {
            int m = m0 + wm + i * 16 + lrow;
            int n = n0 + wn + j * 8 + (lane & 3) * 2;
            *(float2*)&C[(long)m * N + n]       = make_float2(acc[i][j][0], acc[i][j][1]);
            *(float2*)&C[(long)(m + 8) * N + n] = make_float2(acc[i][j][2], acc[i][j][3]);
        }
    }
}

// ===================== GEMM2 (tf32 tensor-core, NN) ========================
// out[b,o,t] = sum_d Wout[o,d]*mid[b,d,t] + bout[o]
// A = Wout [512][512] K-contig, B = mid_b [512][1024] N-contig
__global__ __launch_bounds__(256, 2)
void k_gemm_out_tc(const float* __restrict__ A, const float* __restrict__ bias,
                   float* __restrict__ out) {
    const float* Bm = g_mid + (long)blockIdx.z * 512 * Tt;
    float*       C  = out   + (long)blockIdx.z * 512 * Tt;
    const int K = 512, N = 1024;

    __shared__ float As[2][128 * 20];
    __shared__ float Bs[2][16 * 136];

    int tid = threadIdx.x;
    int warp = tid >> 5, lane = tid & 31;
    int wm = (warp >> 2) * 64;
    int wn = (warp & 3) * 32;
    int m0 = blockIdx.y * 128, n0 = blockIdx.x * 128;
    int lrow = lane >> 2, lcol = lane & 3;

    float acc[4][4][4];
    #pragma unroll
    for (int i = 0; i < 4; i++)
        #pragma unroll
        for (int j = 0; j < 4; j++)
            #pragma unroll
            for (int r = 0; r < 4; r++) acc[i][j][r] = 0.f;

    int arow = tid >> 2;
    int ak   = (tid & 3) * 4;
    int brow = tid >> 5;               // 0..7 (x2)
    int bn   = (tid & 31) * 4;

    // prologue
    {
        #pragma unroll
        for (int l = 0; l < 2; l++) {
            int row = arow + l * 64;
            cp16(&As[0][row * 20 + ak], &A[(long)(m0 + row) * K + ak]);
            int kr = brow + l * 8;
            cp16(&Bs[0][kr * 136 + bn], &Bm[(long)kr * N + n0 + bn]);
        }
        CP_COMMIT();
    }

    for (int kt = 0; kt < 32; kt++) {
        int buf = kt & 1;
        if (kt + 1 < 32) {
            int k0 = (kt + 1) * 16;
            #pragma unroll
            for (int l = 0; l < 2; l++) {
                int row = arow + l * 64;
                cp16(&As[buf ^ 1][row * 20 + ak], &A[(long)(m0 + row) * K + k0 + ak]);
                int kr = brow + l * 8;
                cp16(&Bs[buf ^ 1][kr * 136 + bn], &Bm[(long)(k0 + kr) * N + n0 + bn]);
            }
            CP_COMMIT();
            CP_WAIT1();
        } else {
            CP_WAIT0();
        }
        __syncthreads();

        #pragma unroll
        for (int ks = 0; ks < 2; ks++) {
            int kb = ks * 8 + lcol;
            uint32_t a[4][4], b[4][2];
            #pragma unroll
            for (int i = 0; i < 4; i++) {
                int m = wm + i * 16 + lrow;
                a[i][0] = f2tf(As[buf][m * 20 + kb]);
                a[i][1] = f2tf(As[buf][(m + 8) * 20 + kb]);
                a[i][2] = f2tf(As[buf][m * 20 + kb + 4]);
                a[i][3] = f2tf(As[buf][(m + 8) * 20 + kb + 4]);
            }
            #pragma unroll
            for (int j = 0; j < 4; j++) {
                int n = wn + j * 8 + lrow;
                b[j][0] = f2tf(Bs[buf][kb * 136 + n]);
                b[j][1] = f2tf(Bs[buf][(kb + 4) * 136 + n]);
            }
            #pragma unroll
            for (int i = 0; i < 4; i++)
                #pragma unroll
                for (int j = 0; j < 4; j++)
                    mma_tf32(acc[i][j], a[i], b[j]);
        }
        __syncthreads();
    }

    #pragma unroll
    for (int i = 0; i < 4; i++) {
        #pragma unroll
        for (int j = 0; j < 4; j++) {
            int m = m0 + wm + i * 16 + lrow;
            int n = n0 + wn + j * 8 + (lane & 3) * 2;
            float bv0 = bias[m], bv1 = bias[m + 8];
            *(float2*)&C[(long)m * N + n] =
                make_float2(acc[i][j][0] + bv0, acc[i][j][1] + bv0);
            *(float2*)&C[(long)(m + 8) * N + n] =
                make_float2(acc[i][j][2] + bv1, acc[i][j][3] + bv1);
        }
    }
}

// ---------------- softmax over t for the k slice ---------------------------
__global__ void k_softmax() {
    int row = blockIdx.x;           // 0..4095 == n*64 + d
    int b = row >> 9, r = row & 511;
    const float* src = g_qkv + ((long)b * 1536 + 512 + r) * Tt;
    float*       dst = g_ks  + (long)row * Tt;
    int tid = threadIdx.x;

    float4 x = reinterpret_cast<const float4*>(src)[tid];
    float m = fmaxf(fmaxf(x.x, x.y), fmaxf(x.z, x.w));
    #pragma unroll
    for (int o = 16; o; o >>= 1) m = fmaxf(m, __shfl_xor_sync(0xffffffffu, m, o));
    __shared__ float sm[8];
    __shared__ float ssum[8];
    if ((tid & 31) == 0) sm[tid >> 5] = m;
    __syncthreads();
    float M = sm[0];
    #pragma unroll
    for (int i = 1; i < 8; i++) M = fmaxf(M, sm[i]);

    float e0 = expf(x.x - M), e1 = expf(x.y - M), e2 = expf(x.z - M), e3 = expf(x.w - M);
    float s = e0 + e1 + e2 + e3;
    #pragma unroll
    for (int o = 16; o; o >>= 1) s += __shfl_xor_sync(0xffffffffu, s, o);
    if ((tid & 31) == 0) ssum[tid >> 5] = s;
    __syncthreads();
    float S = 0.f;
    #pragma unroll
    for (int i = 0; i < 8; i++) S += ssum[i];
    float inv = 1.f / S;
    float4 out = make_float4(e0 * inv, e1 * inv, e2 * inv, e3 * inv);
    reinterpret_cast<float4*>(dst)[tid] = out;
}

// ---------------- context partials: ctx[n,d,e] = sum_t ks*v ----------------
__global__ __launch_bounds__(256)
void k_ctx_partial() {
    int n = blockIdx.y, s = blockIdx.x;   // s in 0..7 (t slice of 128)
    int b = n >> 3, h = n & 7;
    const float* Kp = g_ks  + (long)n * DKd * Tt;
    const float* Vp = g_qkv + ((long)b * 1536 + 1024 + h * 64) * Tt;

    __shared__ float Ks[64][68];          // [tt][d]
    __shared__ float Vs[64][68];          // [tt][e]
    int tid = threadIdx.x, tx = tid & 15, ty = tid >> 4;
    float acc[4][4] = {};

    for (int c = 0; c < 2; c++) {
        int t0 = s * 128 + c * 64;
        #pragma unroll
        for (int l = 0; l < 4; l++) {
            int idx = tid + l * 256;
            int d  = idx >> 4;
            int tv = (idx & 15) * 4;
            float4 a = *(const float4*)&Kp[(long)d * Tt + t0 + tv];
            Ks[tv + 0][d] = a.x; Ks[tv + 1][d] = a.y; Ks[tv + 2][d] = a.z; Ks[tv + 3][d] = a.w;
            float4 v = *(const float4*)&Vp[(long)d * Tt + t0 + tv];
            Vs[tv + 0][d] = v.x; Vs[tv + 1][d] = v.y; Vs[tv + 2][d] = v.z; Vs[tv + 3][d] = v.w;
        }
        __syncthreads();
        #pragma unroll 8
        for (int tt = 0; tt < 64; tt++) {
            float a[4], v[4];
            *(float4*)a = *(const float4*)&Ks[tt][ty * 4];
            *(float4*)v = *(const float4*)&Vs[tt][tx * 4];
            #pragma unroll
            for (int i = 0; i < 4; i++)
                #pragma unroll
                for (int j = 0; j < 4; j++) acc[i][j] += a[i] * v[j];
        }
        __syncthreads();
    }
    float* dst = g_ctxp + ((long)s * NHn + n) * 4096;
    #pragma unroll
    for (int i = 0; i < 4; i++) {
        float4 c = make_float4(acc[i][0], acc[i][1], acc[i][2], acc[i][3]);
        *(float4*)&dst[(ty * 4 + i) * 64 + tx * 4] = c;
    }
}

__global__ void k_ctx_reduce() {
    int gid = blockIdx.x * 256 + threadIdx.x;  // 262144
    float s = 0.f;
    #pragma unroll
    for (int p = 0; p < 8; p++) s += g_ctxp[(long)p * 262144 + gid];
    g_ctx[gid] = s;
}

// ---------------- content: mid[n,e,t] = sum_d ctx[n,d,e]*q[n,d,t] ----------
__global__ __launch_bounds__(256)
void k_content() {
    int n = blockIdx.y;
    int t = blockIdx.x * 256 + threadIdx.x;
    int b = n >> 3, h = n & 7;
    const float* Q = g_qkv + ((long)b * 1536 + h * 64) * Tt;

    __shared__ float cs[4096];
    const float4* csrc = (const float4*)(g_ctx + (long)n * 4096);
    for (int i = threadIdx.x; i < 1024; i += 256) ((float4*)cs)[i] = csrc[i];
    __syncthreads();

    float q[64];
    #pragma unroll
    for (int d = 0; d < 64; d++) q[d] = Q[(long)d * Tt + t];

    float* dst = g_mid + ((long)b * 512 + h * 64) * Tt + t;
    #pragma unroll
    for (int e0 = 0; e0 < 64; e0 += 4) {
        float4 a = make_float4(0.f, 0.f, 0.f, 0.f);
        #pragma unroll
        for (int d = 0; d < 64; d++) {
            float4 c = *(const float4*)&cs[d * 64 + e0];
            a.x += c.x * q[d]; a.y += c.y * q[d];
            a.z += c.z * q[d]; a.w += c.w * q[d];
        }
        dst[(long)(e0 + 0) * Tt] = a.x;
        dst[(long)(e0 + 1) * Tt] = a.y;
        dst[(long)(e0 + 2) * Tt] = a.z;
        dst[(long)(e0 + 3) * Tt] = a.w;
    }
}

// ---------------- S[n,t] = sum_d q[n,d,t] * PsumT[d,t] ---------------------
__global__ void k_S() {
    int n = blockIdx.y;
    int t = blockIdx.x * 256 + threadIdx.x;
    int b = n >> 3, h = n & 7;
    const float* Q = g_qkv + ((long)b * 1536 + h * 64) * Tt;
    float s = 0.f;
    #pragma unroll
    for (int d = 0; d < 64; d++) s += Q[(long)d * Tt + t] * g_P[d * Tt + t];
    g_S[n * Tt + t] = s;
}

// ---------------- BN stats partials over rel = v*S -------------------------
__global__ void k_bnstats() {
    int n = blockIdx.y, e = blockIdx.x;
    int b = n >> 3, h = n & 7;
    const float* V  = g_qkv + ((long)b * 1536 + 1024 + h * 64 + e) * Tt;
    const float* Sp = g_S + (long)n * Tt;
    int tid = threadIdx.x;
    float4 v = ((const float4*)V)[tid];
    float4 s = ((const float4*)Sp)[tid];
    float r0 = v.x * s.x, r1 = v.y * s.y, r2 = v.z * s.z, r3 = v.w * s.w;
    float sum = r0 + r1 + r2 + r3;
    float sq  = r0 * r0 + r1 * r1 + r2 * r2 + r3 * r3;
    #pragma unroll
    for (int o = 16; o; o >>= 1) {
        sum += __shfl_xor_sync(0xffffffffu, sum, o);
        sq  += __shfl_xor_sync(0xffffffffu, sq,  o);
    }
    __shared__ float ws[8], wq[8];
    if ((tid & 31) == 0) { ws[tid >> 5] = sum; wq[tid >> 5] = sq; }
    __syncthreads();
    if (tid == 0) {
        float S = 0.f, Q = 0.f;
        #pragma unroll
        for (int i = 0; i < 8; i++) { S += ws[i]; Q += wq[i]; }
        g_bns[e * 64 + n] = S;
        g_bnq[e * 64 + n] = Q;
    }
}

__global__ void k_bnred(const float* __restrict__ gamma, const float* __restrict__ beta) {
    int e = threadIdx.x;  // 64
    float s = 0.f, q = 0.f;
    #pragma unroll
    for (int n = 0; n < 64; n++) { s += g_bns[e * 64 + n]; q += g_bnq[e * 64 + n]; }
    const float cnt = (float)(NHn * Tt);
    float mu  = s / cnt;
    float var = q / cnt - mu * mu;
    float sc  = gamma[e] * rsqrtf(var + EPSf);
    g_sc[e] = sc;
    g_sh[e] = beta[e] - mu * sc;
}

// ---------------- mid += BN(v*S) -------------------------------------------
__global__ void k_reladd() {
    int row = blockIdx.x;             // 0..4095 == b*512 + h*64 + e == n*64+e
    int e = row & 63;
    int n = row >> 6;
    int b = n >> 3, h = n & 7;
    const float* V  = g_qkv + ((long)b * 1536 + 1024 + h * 64 + e) * Tt;
    const float* Sp = g_S + (long)n * Tt;
    float*       D  = g_mid + (long)row * Tt;
    float sc = g_sc[e], sh = g_sh[e];
    int tid = threadIdx.x;
    float4 v = ((const float4*)V)[tid];
    float4 s = ((const float4*)Sp)[tid];
    float4 m = ((const float4*)D)[tid];
    m.x += v.x * s.x * sc + sh;
    m.y += v.y * s.y * sc + sh;
    m.z += v.z * s.z * sc + sh;
    m.w += v.w * s.w * sc + sh;
    ((float4*)D)[tid] = m;
}

// ---------------- launcher -------------------------------------------------
extern "C" void kernel_launch(void* const* d_in, const int* in_sizes, int n_in,
                              void* d_out, int out_size) {
    const float* x      = (const float*)d_in[0];   // (8,1024,512)
    const float* Wqkv   = (const float*)d_in[1];   // (1536,512)
    const float* Wout   = (const float*)d_in[2];   // (512,512)
    const float* bout   = (const float*)d_in[3];   // (512)
    const float* relpos = (const float*)d_in[4];   // (63,64)
    const float* gamma  = (const float*)d_in[5];   // (64)
    const float* beta   = (const float*)d_in[6];   // (64)
    float* out = (float*)d_out;                    // (8,512,1024)

    k_prep<<<256, 256>>>(relpos);
    k_gemm_qkv_tc<<<dim3(8, 12, 8), 256>>>(Wqkv, x);
    k_softmax<<<4096, 256>>>();
    k_ctx_partial<<<dim3(8, 64), 256>>>();
    k_ctx_reduce<<<1024, 256>>>();
    k_content<<<dim3(4, 64), 256>>>();
    k_S<<<dim3(4, 64), 256>>>();
    k_bnstats<<<dim3(64, 64), 256>>>();
    k_bnred<<<1, 64>>>(gamma, beta);
    k_reladd<<<4096, 256>>>();
    k_gemm_out_tc<<<dim3(8, 4, 8), 256>>>(Wout, bout, out);
}

// round 3
// speedup vs baseline: 2.1272x; 1.0090x over previous
#include <cuda_runtime.h>
#include <math.h>
#include <stdint.h>

#define Bb   8
#define Tt   1024
#define DIMf 512
#define Hh   8
#define DKd  64
#define DHh  512
#define NHn  64
#define EPSf 1e-5f

// ---------------- scratch ---------------------------------------------------
__device__ float g_qkv[Bb * 3 * DHh * Tt];
__device__ float g_ctxp[4 * NHn * DKd * DKd];
__device__ float g_mid [Bb * DHh * Tt];
__device__ float g_S   [NHn * Tt];
__device__ float g_P   [DKd * Tt];
__device__ float g_M   [NHn * DKd];
__device__ float g_invZ[NHn * DKd];
__device__ float g_bns [DKd * NHn];
__device__ float g_bnq [DKd * NHn];
__device__ float g_sc  [DKd];
__device__ float g_sh  [DKd];

// ---------------- PTX helpers -----------------------------------------------
__device__ __forceinline__ void cp16(void* smem, const void* gmem) {
    uint32_t s = (uint32_t)__cvta_generic_to_shared(smem);
    asm volatile("cp.async.cg.shared.global [%0], [%1], 16;\n" :: "r"(s), "l"(gmem));
}
#define CP_COMMIT() asm volatile("cp.async.commit_group;\n")
#define CP_WAIT0()  asm volatile("cp.async.wait_group 0;\n")
#define CP_WAIT1()  asm volatile("cp.async.wait_group 1;\n")

__device__ __forceinline__ uint32_t f2tf(float x) {
    uint32_t r;
    asm("cvt.rna.tf32.f32 %0, %1;" : "=r"(r) : "f"(x));
    return r;
}

__device__ __forceinline__ void mma_tf32(float* c, const uint32_t* a, const uint32_t* b) {
    asm volatile(
        "mma.sync.aligned.m16n8k8.row.col.f32.tf32.tf32.f32 "
        "{%0,%1,%2,%3}, {%4,%5,%6,%7}, {%8,%9}, {%0,%1,%2,%3};\n"
        : "+f"(c[0]), "+f"(c[1]), "+f"(c[2]), "+f"(c[3])
        : "r"(a[0]), "r"(a[1]), "r"(a[2]), "r"(a[3]), "r"(b[0]), "r"(b[1]));
}

// ---------------- rel-pos band prefix ---------------------------------------
__global__ void k_prep(const float* __restrict__ relpos) {
    int gid = blockIdx.x * 256 + threadIdx.x;
    int d = gid >> 10, t = gid & 1023;
    int lo = 31 - t;    if (lo < 0)  lo = 0;
    int hi = 1054 - t;  if (hi > 62) hi = 62;
    float s = 0.f;
    for (int ri = lo; ri <= hi; ri++) s += relpos[ri * DKd + d];
    g_P[d * Tt + t] = s;
}

// ===================== GEMM1 (tf32, TN, 4 warps 64x64) =====================
__global__ __launch_bounds__(128, 2)
void k_gemm_qkv_tc(const float* __restrict__ A, const float* __restrict__ x) {
    const float* Bm = x + (long)blockIdx.z * Tt * DIMf;
    float*       C  = g_qkv + (long)blockIdx.z * 1536 * Tt;
    const int K = 512, N = 1024;

    __shared__ float As[2][128 * 20];
    __shared__ float Bs[2][128 * 20];

    int tid = threadIdx.x;
    int warp = tid >> 5, lane = tid & 31;
    int wm = (warp >> 1) * 64;
    int wn = (warp & 1) * 64;
    int m0 = blockIdx.y * 128, n0 = blockIdx.x * 128;
    int lrow = lane >> 2, lcol = lane & 3;

    float acc[4][8][4];
    #pragma unroll
    for (int i = 0; i < 4; i++)
        #pragma unroll
        for (int j = 0; j < 8; j++)
            #pragma unroll
            for (int r = 0; r < 4; r++) acc[i][j][r] = 0.f;

    int crow = tid >> 2;          // 0..31
    int ck   = (tid & 3) * 4;

    {
        #pragma unroll
        for (int l = 0; l < 4; l++) {
            int row = crow + l * 32;
            cp16(&As[0][row * 20 + ck], &A [(long)(m0 + row) * K + ck]);
            cp16(&Bs[0][row * 20 + ck], &Bm[(long)(n0 + row) * K + ck]);
        }
        CP_COMMIT();
    }

    for (int kt = 0; kt < 32; kt++) {
        int buf = kt & 1;
        if (kt + 1 < 32) {
            int k0 = (kt + 1) * 16;
            #pragma unroll
            for (int l = 0; l < 4; l++) {
                int row = crow + l * 32;
                cp16(&As[buf ^ 1][row * 20 + ck], &A [(long)(m0 + row) * K + k0 + ck]);
                cp16(&Bs[buf ^ 1][row * 20 + ck], &Bm[(long)(n0 + row) * K + k0 + ck]);
            }
            CP_COMMIT();
            CP_WAIT1();
        } else {
            CP_WAIT0();
        }
        __syncthreads();

        #pragma unroll
        for (int ks = 0; ks < 2; ks++) {
            int kb = ks * 8 + lcol;
            uint32_t a[4][4], b[8][2];
            #pragma unroll
            for (int i = 0; i < 4; i++) {
                int m = wm + i * 16 + lrow;
                a[i][0] = f2tf(As[buf][m * 20 + kb]);
                a[i][1] = f2tf(As[buf][(m + 8) * 20 + kb]);
                a[i][2] = f2tf(As[buf][m * 20 + kb + 4]);
                a[i][3] = f2tf(As[buf][(m + 8) * 20 + kb + 4]);
            }
            #pragma unroll
            for (int j = 0; j < 8; j++) {
                int n = wn + j * 8 + lrow;
                b[j][0] = f2tf(Bs[buf][n * 20 + kb]);
                b[j][1] = f2tf(Bs[buf][n * 20 + kb + 4]);
            }
            #pragma unroll
            for (int i = 0; i < 4; i++)
                #pragma unroll
                for (int j = 0; j < 8; j++)
                    mma_tf32(acc[i][j], a[i], b[j]);
        }
        __syncthreads();
    }

    #pragma unroll
    for (int i = 0; i < 4; i++) {
        #pragma unroll
        for (int j = 0; j < 8; j++) {
            int m = m0 + wm + i * 16 + lrow;
            int n = n0 + wn + j * 8 + (lane & 3) * 2;
            *(float2*)&C[(long)m * N + n]       = make_float2(acc[i][j][0], acc[i][j][1]);
            *(float2*)&C[(long)(m + 8) * N + n] = make_float2(acc[i][j][2], acc[i][j][3]);
        }
    }
}

// ===================== GEMM2 (tf32, NN, 4 warps 64x64) =====================
__global__ __launch_bounds__(128, 2)
void k_gemm_out_tc(const float* __restrict__ A, const float* __restrict__ bias,
                   float* __restrict__ out) {
    const float* Bm = g_mid + (long)blockIdx.z * 512 * Tt;
    float*       C  = out   + (long)blockIdx.z * 512 * Tt;
    const int K = 512, N = 1024;

    __shared__ float As[2][128 * 20];
    __shared__ float Bs[2][16 * 136];

    int tid = threadIdx.x;
    int warp = tid >> 5, lane = tid & 31;
    int wm = (warp >> 1) * 64;
    int wn = (warp & 1) * 64;
    int m0 = blockIdx.y * 128, n0 = blockIdx.x * 128;
    int lrow = lane >> 2, lcol = lane & 3;

    float acc[4][8][4];
    #pragma unroll
    for (int i = 0; i < 4; i++)
        #pragma unroll
        for (int j = 0; j < 8; j++)
            #pragma unroll
            for (int r = 0; r < 4; r++) acc[i][j][r] = 0.f;

    int arow = tid >> 2;           // 0..31
    int ak   = (tid & 3) * 4;
    int brow = tid >> 5;           // 0..3
    int bn   = (tid & 31) * 4;

    {
        #pragma unroll
        for (int l = 0; l < 4; l++) {
            int row = arow + l * 32;
            cp16(&As[0][row * 20 + ak], &A[(long)(m0 + row) * K + ak]);
            int kr = brow + l * 4;
            cp16(&Bs[0][kr * 136 + bn], &Bm[(long)kr * N + n0 + bn]);
        }
        CP_COMMIT();
    }

    for (int kt = 0; kt < 32; kt++) {
        int buf = kt & 1;
        if (kt + 1 < 32) {
            int k0 = (kt + 1) * 16;
            #pragma unroll
            for (int l = 0; l < 4; l++) {
                int row = arow + l * 32;
                cp16(&As[buf ^ 1][row * 20 + ak], &A[(long)(m0 + row) * K + k0 + ak]);
                int kr = brow + l * 4;
                cp16(&Bs[buf ^ 1][kr * 136 + bn], &Bm[(long)(k0 + kr) * N + n0 + bn]);
            }
            CP_COMMIT();
            CP_WAIT1();
        } else {
            CP_WAIT0();
        }
        __syncthreads();

        #pragma unroll
        for (int ks = 0; ks < 2; ks++) {
            int kb = ks * 8 + lcol;
            uint32_t a[4][4], b[8][2];
            #pragma unroll
            for (int i = 0; i < 4; i++) {
                int m = wm + i * 16 + lrow;
                a[i][0] = f2tf(As[buf][m * 20 + kb]);
                a[i][1] = f2tf(As[buf][(m + 8) * 20 + kb]);
                a[i][2] = f2tf(As[buf][m * 20 + kb + 4]);
                a[i][3] = f2tf(As[buf][(m + 8) * 20 + kb + 4]);
            }
            #pragma unroll
            for (int j = 0; j < 8; j++) {
                int n = wn + j * 8 + lrow;
                b[j][0] = f2tf(Bs[buf][kb * 136 + n]);
                b[j][1] = f2tf(Bs[buf][(kb + 4) * 136 + n]);
            }
            #pragma unroll
            for (int i = 0; i < 4; i++)
                #pragma unroll
                for (int j = 0; j < 8; j++)
                    mma_tf32(acc[i][j], a[i], b[j]);
        }
        __syncthreads();
    }

    #pragma unroll
    for (int i = 0; i < 4; i++) {
        #pragma unroll
        for (int j = 0; j < 8; j++) {
            int m = m0 + wm + i * 16 + lrow;
            int n = n0 + wn + j * 8 + (lane & 3) * 2;
            float bv0 = bias[m], bv1 = bias[m + 8];
            *(float2*)&C[(long)m * N + n] =
                make_float2(acc[i][j][0] + bv0, acc[i][j][1] + bv0);
            *(float2*)&C[(long)(m + 8) * N + n] =
                make_float2(acc[i][j][2] + bv1, acc[i][j][3] + bv1);
        }
    }
}

// ---------------- per-row softmax stats (max, 1/Z) --------------------------
__global__ void k_mz() {
    int n = blockIdx.x;                  // 0..63
    int warp = threadIdx.x >> 5, lane = threadIdx.x & 31;
    int b = n >> 3, h = n & 7;
    const float* base = g_qkv + ((long)b * 1536 + 512 + h * 64) * Tt;
    for (int it = 0; it < 8; it++) {
        int d = warp * 8 + it;
        const float* src = base + (long)d * Tt;
        float4 v[8];
        float m = -1e30f;
        #pragma unroll
        for (int p = 0; p < 8; p++) {
            v[p] = *(const float4*)&src[lane * 4 + p * 128];
            m = fmaxf(m, fmaxf(fmaxf(v[p].x, v[p].y), fmaxf(v[p].z, v[p].w)));
        }
        #pragma unroll
        for (int o = 16; o; o >>= 1) m = fmaxf(m, __shfl_xor_sync(0xffffffffu, m, o));
        float s = 0.f;
        #pragma unroll
        for (int p = 0; p < 8; p++) {
            s += exp2f((v[p].x - m) * 1.44269504f);
            s += exp2f((v[p].y - m) * 1.44269504f);
            s += exp2f((v[p].z - m) * 1.44269504f);
            s += exp2f((v[p].w - m) * 1.44269504f);
        }
        #pragma unroll
        for (int o = 16; o; o >>= 1) s += __shfl_xor_sync(0xffffffffu, s, o);
        if (lane == 0) {
            g_M[n * 64 + d] = m;
            g_invZ[n * 64 + d] = 1.f / s;
        }
    }
}

// ---------------- ctx via tf32 mma with fused exp ---------------------------
// ctxp[s][n][d][e] = sum_{t in slice s} softmax(k)[d,t] * v[e,t]
__global__ __launch_bounds__(128)
void k_ctx_mma() {
    int s = blockIdx.x, n = blockIdx.y;
    int b = n >> 3, h = n & 7;
    const float* Kraw = g_qkv + ((long)b * 1536 + 512  + h * 64) * Tt;
    const float* Vp   = g_qkv + ((long)b * 1536 + 1024 + h * 64) * Tt;

    __shared__ float Ks[64 * 68];
    __shared__ float Vs[64 * 68];
    __shared__ float sM[64], sZ[64];

    int tid = threadIdx.x;
    if (tid < 64) { sM[tid] = g_M[n * 64 + tid]; sZ[tid] = g_invZ[n * 64 + tid]; }

    int warp = tid >> 5, lane = tid & 31;
    int wm = (warp >> 1) * 32, wn = (warp & 1) * 32;
    int lrow = lane >> 2, lcol = lane & 3;
    int tv = (tid & 15) * 4, dl = tid >> 4;    // dl 0..7

    float acc[2][4][4];
    #pragma unroll
    for (int i = 0; i < 2; i++)
        #pragma unroll
        for (int j = 0; j < 4; j++)
            #pragma unroll
            for (int r = 0; r < 4; r++) acc[i][j][r] = 0.f;

    __syncthreads();

    for (int c = 0; c < 4; c++) {
        int t0 = s * 256 + c * 64;
        #pragma unroll
        for (int dd = 0; dd < 8; dd++) {
            int e = dd * 8 + dl;
            cp16(&Vs[e * 68 + tv], &Vp[(long)e * Tt + t0 + tv]);
        }
        CP_COMMIT();
        #pragma unroll
        for (int dd = 0; dd < 8; dd++) {
            int d = dd * 8 + dl;
            float4 kv = *(const float4*)&Kraw[(long)d * Tt + t0 + tv];
            float M = sM[d], iz = sZ[d];
            float4 o;
            o.x = exp2f((kv.x - M) * 1.44269504f) * iz;
            o.y = exp2f((kv.y - M) * 1.44269504f) * iz;
            o.z = exp2f((kv.z - M) * 1.44269504f) * iz;
            o.w = exp2f((kv.w - M) * 1.44269504f) * iz;
            *(float4*)&Ks[d * 68 + tv] = o;
        }
        CP_WAIT0();
        __syncthreads();

        #pragma unroll
        for (int k8 = 0; k8 < 8; k8++) {
            int kb = k8 * 8 + lcol;
            uint32_t a[2][4], bf[4][2];
            #pragma unroll
            for (int i = 0; i < 2; i++) {
                int m = wm + i * 16 + lrow;
                a[i][0] = f2tf(Ks[m * 68 + kb]);
                a[i][1] = f2tf(Ks[(m + 8) * 68 + kb]);
                a[i][2] = f2tf(Ks[m * 68 + kb + 4]);
                a[i][3] = f2tf(Ks[(m + 8) * 68 + kb + 4]);
            }
            #pragma unroll
            for (int j = 0; j < 4; j++) {
                int e = wn + j * 8 + lrow;
                bf[j][0] = f2tf(Vs[e * 68 + kb]);
                bf[j][1] = f2tf(Vs[e * 68 + kb + 4]);
            }
            #pragma unroll
            for (int i = 0; i < 2; i++)
                #pragma unroll
                for (int j = 0; j < 4; j++)
                    mma_tf32(acc[i][j], a[i], bf[j]);
        }
        __syncthreads();
    }

    float* dst = g_ctxp + ((long)s * NHn + n) * 4096;
    #pragma unroll
    for (int i = 0; i < 2; i++) {
        #pragma unroll
        for (int j = 0; j < 4; j++) {
            int d = wm + i * 16 + lrow;
            int e = wn + j * 8 + (lane & 3) * 2;
            *(float2*)&dst[d * 64 + e]       = make_float2(acc[i][j][0], acc[i][j][1]);
            *(float2*)&dst[(d + 8) * 64 + e] = make_float2(acc[i][j][2], acc[i][j][3]);
        }
    }
}

// ---------------- content + S (fused ctx-reduce) ----------------------------
__global__ __launch_bounds__(256)
void k_content() {
    int n = blockIdx.y;
    int t = blockIdx.x * 256 + threadIdx.x;
    int b = n >> 3, h = n & 7;
    const float* Q = g_qkv + ((long)b * 1536 + h * 64) * Tt;

    __shared__ float cs[4096];
    {
        const float4* p0 = (const float4*)(g_ctxp + (long)n * 4096);
        const float4* p1 = (const float4*)(g_ctxp + (long)(NHn + n) * 4096);
        const float4* p2 = (const float4*)(g_ctxp + (long)(2 * NHn + n) * 4096);
        const float4* p3 = (const float4*)(g_ctxp + (long)(3 * NHn + n) * 4096);
        for (int i = threadIdx.x; i < 1024; i += 256) {
            float4 a = p0[i], b1 = p1[i], c = p2[i], d = p3[i];
            a.x += b1.x + c.x + d.x; a.y += b1.y + c.y + d.y;
            a.z += b1.z + c.z + d.z; a.w += b1.w + c.w + d.w;
            ((float4*)cs)[i] = a;
        }
    }
    __syncthreads();

    float q[64];
    float S = 0.f;
    #pragma unroll
    for (int d = 0; d < 64; d++) {
        q[d] = Q[(long)d * Tt + t];
        S += q[d] * g_P[d * Tt + t];
    }
    g_S[n * Tt + t] = S;

    float* dst = g_mid + ((long)b * 512 + h * 64) * Tt + t;
    #pragma unroll
    for (int e0 = 0; e0 < 64; e0 += 4) {
        float4 a = make_float4(0.f, 0.f, 0.f, 0.f);
        #pragma unroll
        for (int d = 0; d < 64; d++) {
            float4 c = *(const float4*)&cs[d * 64 + e0];
            a.x += c.x * q[d]; a.y += c.y * q[d];
            a.z += c.z * q[d]; a.w += c.w * q[d];
        }
        dst[(long)(e0 + 0) * Tt] = a.x;
        dst[(long)(e0 + 1) * Tt] = a.y;
        dst[(long)(e0 + 2) * Tt] = a.z;
        dst[(long)(e0 + 3) * Tt] = a.w;
    }
}

// ---------------- BN stats ---------------------------------------------------
__global__ void k_bnstats() {
    int n = blockIdx.y, e = blockIdx.x;
    int b = n >> 3, h = n & 7;
    const float* V  = g_qkv + ((long)b * 1536 + 1024 + h * 64 + e) * Tt;
    const float* Sp = g_S + (long)n * Tt;
    int tid = threadIdx.x;
    float4 v = ((const float4*)V)[tid];
    float4 s = ((const float4*)Sp)[tid];
    float r0 = v.x * s.x, r1 = v.y * s.y, r2 = v.z * s.z, r3 = v.w * s.w;
    float sum = r0 + r1 + r2 + r3;
    float sq  = r0 * r0 + r1 * r1 + r2 * r2 + r3 * r3;
    #pragma unroll
    for (int o = 16; o; o >>= 1) {
        sum += __shfl_xor_sync(0xffffffffu, sum, o);
        sq  += __shfl_xor_sync(0xffffffffu, sq,  o);
    }
    __shared__ float ws[8], wq[8];
    if ((tid & 31) == 0) { ws[tid >> 5] = sum; wq[tid >> 5] = sq; }
    __syncthreads();
    if (tid == 0) {
        float S = 0.f, Q = 0.f;
        #pragma unroll
        for (int i = 0; i < 8; i++) { S += ws[i]; Q += wq[i]; }
        g_bns[e * 64 + n] = S;
        g_bnq[e * 64 + n] = Q;
    }
}

__global__ void k_bnred(const float* __restrict__ gamma, const float* __restrict__ beta) {
    int e = threadIdx.x;
    float s = 0.f, q = 0.f;
    #pragma unroll
    for (int n = 0; n < 64; n++) { s += g_bns[e * 64 + n]; q += g_bnq[e * 64 + n]; }
    const float cnt = (float)(NHn * Tt);
    float mu  = s / cnt;
    float var = q / cnt - mu * mu;
    float sc  = gamma[e] * rsqrtf(var + EPSf);
    g_sc[e] = sc;
    g_sh[e] = beta[e] - mu * sc;
}

// ---------------- mid += BN(v*S) ---------------------------------------------
__global__ void k_reladd() {
    int row = blockIdx.x;
    int e = row & 63;
    int n = row >> 6;
    int b = n >> 3, h = n & 7;
    const float* V  = g_qkv + ((long)b * 1536 + 1024 + h * 64 + e) * Tt;
    const float* Sp = g_S + (long)n * Tt;
    float*       D  = g_mid + (long)row * Tt;
    float sc = g_sc[e], sh = g_sh[e];
    int tid = threadIdx.x;
    float4 v = ((const float4*)V)[tid];
    float4 s = ((const float4*)Sp)[tid];
    float4 m = ((const float4*)D)[tid];
    m.x += v.x * s.x * sc + sh;
    m.y += v.y * s.y * sc + sh;
    m.z += v.z * s.z * sc + sh;
    m.w += v.w * s.w * sc + sh;
    ((float4*)D)[tid] = m;
}

// ---------------- launcher ---------------------------------------------------
extern "C" void kernel_launch(void* const* d_in, const int* in_sizes, int n_in,
                              void* d_out, int out_size) {
    const float* x      = (const float*)d_in[0];
    const float* Wqkv   = (const float*)d_in[1];
    const float* Wout   = (const float*)d_in[2];
    const float* bout   = (const float*)d_in[3];
    const float* relpos = (const float*)d_in[4];
    const float* gamma  = (const float*)d_in[5];
    const float* beta   = (const float*)d_in[6];
    float* out = (float*)d_out;

    k_prep<<<256, 256>>>(relpos);
    k_gemm_qkv_tc<<<dim3(8, 12, 8), 128>>>(Wqkv, x);
    k_mz<<<64, 256>>>();
    k_ctx_mma<<<dim3(4, 64), 128>>>();
    k_content<<<dim3(4, 64), 256>>>();
    k_bnstats<<<dim3(64, 64), 256>>>();
    k_bnred<<<1, 64>>>(gamma, beta);
    k_reladd<<<4096, 256>>>();
    k_gemm_out_tc<<<dim3(8, 4, 8), 128>>>(Wout, bout, out);
}

// round 5
// speedup vs baseline: 2.7878x; 1.3106x over previous
#include <cuda_runtime.h>
#include <cuda_fp16.h>
#include <math.h>
#include <stdint.h>

#define Bb   8
#define Tt   1024
#define DIMf 512
#define Hh   8
#define DKd  64
#define DHh  512
#define NHn  64
#define EPSf 1e-5f

// ---------------- scratch ---------------------------------------------------
__device__ float  g_qkv[Bb * 3 * DHh * Tt];
__device__ __half g_Wh [1536 * 512];
__device__ __half g_xh [Bb * Tt * DIMf];
__device__ __half g_Woh[512 * 512];
__device__ __half g_midh[Bb * DHh * Tt];
__device__ float  g_ctxp[4 * NHn * DKd * DKd];
__device__ float  g_mid [Bb * DHh * Tt];
__device__ float  g_S   [NHn * Tt];
__device__ float  g_P   [DKd * Tt];
__device__ float  g_M   [NHn * DKd];
__device__ float  g_invZ[NHn * DKd];
__device__ float  g_bns [DKd * NHn];
__device__ float  g_bnq [DKd * NHn];
__device__ float  g_sc  [DKd];
__device__ float  g_sh  [DKd];

// ---------------- PTX helpers -----------------------------------------------
__device__ __forceinline__ void cp16(void* smem, const void* gmem) {
    uint32_t s = (uint32_t)__cvta_generic_to_shared(smem);
    asm volatile("cp.async.cg.shared.global [%0], [%1], 16;\n" :: "r"(s), "l"(gmem));
}
__device__ __forceinline__ void cp16s(uint32_t s, const void* gmem) {
    asm volatile("cp.async.cg.shared.global [%0], [%1], 16;\n" :: "r"(s), "l"(gmem));
}
#define CP_COMMIT() asm volatile("cp.async.commit_group;\n")
#define CP_WAIT0()  asm volatile("cp.async.wait_group 0;\n")
#define CP_WAIT1()  asm volatile("cp.async.wait_group 1;\n")

__device__ __forceinline__ uint32_t smem_u32(const void* p) {
    uint32_t a;
    asm("{ .reg .u64 t; cvta.to.shared.u64 t, %1; cvt.u32.u64 %0, t; }" : "=r"(a) : "l"(p));
    return a;
}

__device__ __forceinline__ uint32_t f2tf(float x) {
    uint32_t r;
    asm("cvt.rna.tf32.f32 %0, %1;" : "=r"(r) : "f"(x));
    return r;
}

__device__ __forceinline__ void mma_tf32(float* c, const uint32_t* a, const uint32_t* b) {
    asm volatile(
        "mma.sync.aligned.m16n8k8.row.col.f32.tf32.tf32.f32 "
        "{%0,%1,%2,%3}, {%4,%5,%6,%7}, {%8,%9}, {%0,%1,%2,%3};\n"
        : "+f"(c[0]), "+f"(c[1]), "+f"(c[2]), "+f"(c[3])
        : "r"(a[0]), "r"(a[1]), "r"(a[2]), "r"(a[3]), "r"(b[0]), "r"(b[1]));
}

__device__ __forceinline__ void mma_f16(float* c, const uint32_t* a, const uint32_t* b) {
    asm volatile(
        "mma.sync.aligned.m16n8k16.row.col.f32.f16.f16.f32 "
        "{%0,%1,%2,%3}, {%4,%5,%6,%7}, {%8,%9}, {%0,%1,%2,%3};\n"
        : "+f"(c[0]), "+f"(c[1]), "+f"(c[2]), "+f"(c[3])
        : "r"(a[0]), "r"(a[1]), "r"(a[2]), "r"(a[3]), "r"(b[0]), "r"(b[1]));
}

__device__ __forceinline__ void ldsm_x4(uint32_t* r, uint32_t addr) {
    asm volatile("ldmatrix.sync.aligned.m8n8.x4.shared.b16 {%0,%1,%2,%3}, [%4];"
        : "=r"(r[0]), "=r"(r[1]), "=r"(r[2]), "=r"(r[3]) : "r"(addr));
}
__device__ __forceinline__ void ldsm_x4t(uint32_t* r, uint32_t addr) {
    asm volatile("ldmatrix.sync.aligned.m8n8.x4.trans.shared.b16 {%0,%1,%2,%3}, [%4];"
        : "=r"(r[0]), "=r"(r[1]), "=r"(r[2]), "=r"(r[3]) : "r"(addr));
}

// ---------------- convert W, x, Wout to fp16 --------------------------------
__global__ void k_round(const float* __restrict__ W, const float* __restrict__ x,
                        const float* __restrict__ Wo) {
    long i = (long)blockIdx.x * 256 + threadIdx.x;   // float4 index
    float4 v;
    __half* dst;
    long j;
    if (i < 196608) {                     // Wqkv: 1536*512/4
        v = ((const float4*)W)[i]; dst = g_Wh; j = i;
    } else if (i < 1245184) {             // x: 8*1024*512/4
        j = i - 196608; v = ((const float4*)x)[j]; dst = g_xh;
    } else {                              // Wout: 512*512/4
        j = i - 1245184; v = ((const float4*)Wo)[j]; dst = g_Woh;
    }
    __half2 p0 = __floats2half2_rn(v.x, v.y);
    __half2 p1 = __floats2half2_rn(v.z, v.w);
    uint2 u;
    u.x = *(const uint32_t*)&p0;
    u.y = *(const uint32_t*)&p1;
    ((uint2*)dst)[j] = u;
}

// ---------------- rel-pos band prefix ---------------------------------------
__global__ void k_prep(const float* __restrict__ relpos) {
    int gid = blockIdx.x * 256 + threadIdx.x;
    int d = gid >> 10, t = gid & 1023;
    int lo = 31 - t;    if (lo < 0)  lo = 0;
    int hi = 1054 - t;  if (hi > 62) hi = 62;
    float s = 0.f;
    for (int ri = lo; ri <= hi; ri++) s += relpos[ri * DKd + d];
    g_P[d * Tt + t] = s;
}

// ===================== GEMM1 (fp16 m16n8k16, TN) ===========================
// qkv[b,m,t] = sum_k Wh[m,k] * xh[b,t,k]   (both K-contig)
__global__ __launch_bounds__(128, 2)
void k_gemm_qkv_h() {
    __shared__ __half As[2][128 * 40];
    __shared__ __half Bs[2][128 * 40];

    int tid = threadIdx.x, warp = tid >> 5, lane = tid & 31;
    int wm = (warp >> 1) * 64, wn = (warp & 1) * 64;
    int m0 = blockIdx.y * 128, n0 = blockIdx.x * 128;
    const __half* A  = g_Wh;
    const __half* Bm = g_xh + (long)blockIdx.z * Tt * DIMf;
    float*        C  = g_qkv + (long)blockIdx.z * 1536 * Tt;

    float acc[4][8][4];
    #pragma unroll
    for (int i = 0; i < 4; i++)
        #pragma unroll
        for (int j = 0; j < 8; j++)
            #pragma unroll
            for (int r = 0; r < 4; r++) acc[i][j][r] = 0.f;

    int g = lane >> 3, r8 = lane & 7;
    int a_off = ((g & 1) * 8 + r8) * 40 + (g >> 1) * 8;   // halves
    int b_off = ((g >> 1) * 8 + r8) * 40 + (g & 1) * 8;

    uint32_t sAs = smem_u32(As), sBs = smem_u32(Bs);

    const __half* arow = A  + (long)(m0 + tid) * 512;
    const __half* brow = Bm + (long)(n0 + tid) * 512;

    // prologue: tile 0
    {
        uint32_t da = sAs + (uint32_t)(tid * 40) * 2;
        uint32_t db = sBs + (uint32_t)(tid * 40) * 2;
        #pragma unroll
        for (int q = 0; q < 4; q++) {
            cp16s(da + q * 16, arow + q * 8);
            cp16s(db + q * 16, brow + q * 8);
        }
        CP_COMMIT();
    }

    for (int kt = 0; kt < 16; kt++) {
        int buf = kt & 1;
        if (kt + 1 < 16) {
            uint32_t da = sAs + (uint32_t)((buf ^ 1) * 5120 + tid * 40) * 2;
            uint32_t db = sBs + (uint32_t)((buf ^ 1) * 5120 + tid * 40) * 2;
            const __half* ap = arow + (kt + 1) * 32;
            const __half* bp = brow + (kt + 1) * 32;
            #pragma unroll
            for (int q = 0; q < 4; q++) {
                cp16s(da + q * 16, ap + q * 8);
                cp16s(db + q * 16, bp + q * 8);
            }
            CP_COMMIT();
            CP_WAIT1();
        } else {
            CP_WAIT0();
        }
        __syncthreads();

        #pragma unroll
        for (int ks = 0; ks < 2; ks++) {
            uint32_t a[4][4], b[8][2];
            #pragma unroll
            for (int i = 0; i < 4; i++)
                ldsm_x4(a[i], sAs + (uint32_t)((buf * 5120 + (wm + i * 16) * 40 + ks * 16) + a_off) * 2);
            #pragma unroll
            for (int p = 0; p < 4; p++) {
                uint32_t r[4];
                ldsm_x4(r, sBs + (uint32_t)((buf * 5120 + (wn + p * 16) * 40 + ks * 16) + b_off) * 2);
                b[p * 2][0] = r[0]; b[p * 2][1] = r[1];
                b[p * 2 + 1][0] = r[2]; b[p * 2 + 1][1] = r[3];
            }
            #pragma unroll
            for (int i = 0; i < 4; i++)
                #pragma unroll
                for (int j = 0; j < 8; j++)
                    mma_f16(acc[i][j], a[i], b[j]);
        }
        __syncthreads();
    }

    int lrow = lane >> 2;
    #pragma unroll
    for (int i = 0; i < 4; i++) {
        #pragma unroll
        for (int j = 0; j < 8; j++) {
            int m = m0 + wm + i * 16 + lrow;
            int n = n0 + wn + j * 8 + (lane & 3) * 2;
            *(float2*)&C[(long)m * Tt + n]       = make_float2(acc[i][j][0], acc[i][j][1]);
            *(float2*)&C[(long)(m + 8) * Tt + n] = make_float2(acc[i][j][2], acc[i][j][3]);
        }
    }
}

// ===================== GEMM2 (fp16 m16n8k16, NN via trans) =================
// out[b,m,t] = sum_k Woh[m,k] * midh[b,k,t] + bias[m]
__global__ __launch_bounds__(128, 2)
void k_gemm_out_h(const float* __restrict__ bias, float* __restrict__ out) {
    __shared__ __half As[2][128 * 40];
    __shared__ __half Bs[2][32 * 136];

    int tid = threadIdx.x, warp = tid >> 5, lane = tid & 31;
    int wm = (warp >> 1) * 64, wn = (warp & 1) * 64;
    int m0 = blockIdx.y * 128, n0 = blockIdx.x * 128;
    const __half* A  = g_Woh;
    const __half* Bm = g_midh + (long)blockIdx.z * 512 * Tt;
    float*        C  = out    + (long)blockIdx.z * 512 * Tt;

    float acc[4][8][4];
    #pragma unroll
    for (int i = 0; i < 4; i++)
        #pragma unroll
        for (int j = 0; j < 8; j++)
            #pragma unroll
            for (int r = 0; r < 4; r++) acc[i][j][r] = 0.f;

    int g = lane >> 3, r8 = lane & 7;
    int a_off  = ((g & 1) * 8 + r8) * 40 + (g >> 1) * 8;
    int bt_off = ((g & 1) * 8 + r8) * 136 + (g >> 1) * 8;

    uint32_t sAs = smem_u32(As), sBs = smem_u32(Bs);

    const __half* arow = A + (long)(m0 + tid) * 512;
    int brw = tid >> 2, bq = tid & 3;                 // brw 0..31
    const __half* brow = Bm + (long)brw * Tt + n0;

    // prologue
    {
        uint32_t da = sAs + (uint32_t)(tid * 40) * 2;
        #pragma unroll
        for (int q = 0; q < 4; q++) cp16s(da + q * 16, arow + q * 8);
        uint32_t db = sBs + (uint32_t)(brw * 136) * 2;
        #pragma unroll
        for (int s = 0; s < 4; s++) {
            int qq = bq * 4 + s;
            cp16s(db + qq * 16, brow + qq * 8);
        }
        CP_COMMIT();
    }

    for (int kt = 0; kt < 16; kt++) {
        int buf = kt & 1;
        if (kt + 1 < 16) {
            int k0 = (kt + 1) * 32;
            uint32_t da = sAs + (uint32_t)((buf ^ 1) * 5120 + tid * 40) * 2;
            const __half* ap = arow + k0;
            #pragma unroll
            for (int q = 0; q < 4; q++) cp16s(da + q * 16, ap + q * 8);
            uint32_t db = sBs + (uint32_t)((buf ^ 1) * 4352 + brw * 136) * 2;
            const __half* bp = brow + (long)k0 * Tt;
            #pragma unroll
            for (int s = 0; s < 4; s++) {
                int qq = bq * 4 + s;
                cp16s(db + qq * 16, bp + qq * 8);
            }
            CP_COMMIT();
            CP_WAIT1();
        } else {
            CP_WAIT0();
        }
        __syncthreads();

        #pragma unroll
        for (int ks = 0; ks < 2; ks++) {
            uint32_t a[4][4], b[8][2];
            #pragma unroll
            for (int i = 0; i < 4; i++)
                ldsm_x4(a[i], sAs + (uint32_t)((buf * 5120 + (wm + i * 16) * 40 + ks * 16) + a_off) * 2);
            #pragma unroll
            for (int p = 0; p < 4; p++) {
                uint32_t r[4];
                ldsm_x4t(r, sBs + (uint32_t)((buf * 4352 + (ks * 16) * 136 + wn + p * 16) + bt_off) * 2);
                b[p * 2][0] = r[0]; b[p * 2][1] = r[1];
                b[p * 2 + 1][0] = r[2]; b[p * 2 + 1][1] = r[3];
            }
            #pragma unroll
            for (int i = 0; i < 4; i++)
                #pragma unroll
                for (int j = 0; j < 8; j++)
                    mma_f16(acc[i][j], a[i], b[j]);
        }
        __syncthreads();
    }

    int lrow = lane >> 2;
    #pragma unroll
    for (int i = 0; i < 4; i++) {
        #pragma unroll
        for (int j = 0; j < 8; j++) {
            int m = m0 + wm + i * 16 + lrow;
            int n = n0 + wn + j * 8 + (lane & 3) * 2;
            float bv0 = bias[m], bv1 = bias[m + 8];
            *(float2*)&C[(long)m * Tt + n] =
                make_float2(acc[i][j][0] + bv0, acc[i][j][1] + bv0);
            *(float2*)&C[(long)(m + 8) * Tt + n] =
                make_float2(acc[i][j][2] + bv1, acc[i][j][3] + bv1);
        }
    }
}

// ---------------- per-row softmax stats (max, 1/Z) --------------------------
__global__ void k_mz() {
    int n = blockIdx.x;
    int warp = threadIdx.x >> 5, lane = threadIdx.x & 31;
    int b = n >> 3, h = n & 7;
    const float* base = g_qkv + ((long)b * 1536 + 512 + h * 64) * Tt;
    for (int it = 0; it < 8; it++) {
        int d = warp * 8 + it;
        const float* src = base + (long)d * Tt;
        float4 v[8];
        float m = -1e30f;
        #pragma unroll
        for (int p = 0; p < 8; p++) {
            v[p] = *(const float4*)&src[lane * 4 + p * 128];
            m = fmaxf(m, fmaxf(fmaxf(v[p].x, v[p].y), fmaxf(v[p].z, v[p].w)));
        }
        #pragma unroll
        for (int o = 16; o; o >>= 1) m = fmaxf(m, __shfl_xor_sync(0xffffffffu, m, o));
        float s = 0.f;
        #pragma unroll
        for (int p = 0; p < 8; p++) {
            s += exp2f((v[p].x - m) * 1.44269504f);
            s += exp2f((v[p].y - m) * 1.44269504f);
            s += exp2f((v[p].z - m) * 1.44269504f);
            s += exp2f((v[p].w - m) * 1.44269504f);
        }
        #pragma unroll
        for (int o = 16; o; o >>= 1) s += __shfl_xor_sync(0xffffffffu, s, o);
        if (lane == 0) {
            g_M[n * 64 + d] = m;
            g_invZ[n * 64 + d] = 1.f / s;
        }
    }
}

// ---------------- ctx via tf32 mma with fused exp ---------------------------
__global__ __launch_bounds__(128)
void k_ctx_mma() {
    int s = blockIdx.x, n = blockIdx.y;
    int b = n >> 3, h = n & 7;
    const float* Kraw = g_qkv + ((long)b * 1536 + 512  + h * 64) * Tt;
    const float* Vp   = g_qkv + ((long)b * 1536 + 1024 + h * 64) * Tt;

    __shared__ float Ks[64 * 68];
    __shared__ float Vs[64 * 68];
    __shared__ float sM[64], sZ[64];

    int tid = threadIdx.x;
    if (tid < 64) { sM[tid] = g_M[n * 64 + tid]; sZ[tid] = g_invZ[n * 64 + tid]; }

    int warp = tid >> 5, lane = tid & 31;
    int wm = (warp >> 1) * 32, wn = (warp & 1) * 32;
    int lrow = lane >> 2, lcol = lane & 3;
    int tv = (tid & 15) * 4, dl = tid >> 4;

    float acc[2][4][4];
    #pragma unroll
    for (int i = 0; i < 2; i++)
        #pragma unroll
        for (int j = 0; j < 4; j++)
            #pragma unroll
            for (int r = 0; r < 4; r++) acc[i][j][r] = 0.f;

    __syncthreads();

    for (int c = 0; c < 4; c++) {
        int t0 = s * 256 + c * 64;
        #pragma unroll
        for (int dd = 0; dd < 8; dd++) {
            int e = dd * 8 + dl;
            cp16(&Vs[e * 68 + tv], &Vp[(long)e * Tt + t0 + tv]);
        }
        CP_COMMIT();
        #pragma unroll
        for (int dd = 0; dd < 8; dd++) {
            int d = dd * 8 + dl;
            float4 kv = *(const float4*)&Kraw[(long)d * Tt + t0 + tv];
            float M = sM[d], iz = sZ[d];
            float4 o;
            o.x = exp2f((kv.x - M) * 1.44269504f) * iz;
            o.y = exp2f((kv.y - M) * 1.44269504f) * iz;
            o.z = exp2f((kv.z - M) * 1.44269504f) * iz;
            o.w = exp2f((kv.w - M) * 1.44269504f) * iz;
            *(float4*)&Ks[d * 68 + tv] = o;
        }
        CP_WAIT0();
        __syncthreads();

        #pragma unroll
        for (int k8 = 0; k8 < 8; k8++) {
            int kb = k8 * 8 + lcol;
            uint32_t a[2][4], bf[4][2];
            #pragma unroll
            for (int i = 0; i < 2; i++) {
                int m = wm + i * 16 + lrow;
                a[i][0] = f2tf(Ks[m * 68 + kb]);
                a[i][1] = f2tf(Ks[(m + 8) * 68 + kb]);
                a[i][2] = f2tf(Ks[m * 68 + kb + 4]);
                a[i][3] = f2tf(Ks[(m + 8) * 68 + kb + 4]);
            }
            #pragma unroll
            for (int j = 0; j < 4; j++) {
                int e = wn + j * 8 + lrow;
                bf[j][0] = f2tf(Vs[e * 68 + kb]);
                bf[j][1] = f2tf(Vs[e * 68 + kb + 4]);
            }
            #pragma unroll
            for (int i = 0; i < 2; i++)
                #pragma unroll
                for (int j = 0; j < 4; j++)
                    mma_tf32(acc[i][j], a[i], bf[j]);
        }
        __syncthreads();
    }

    float* dst = g_ctxp + ((long)s * NHn + n) * 4096;
    #pragma unroll
    for (int i = 0; i < 2; i++) {
        #pragma unroll
        for (int j = 0; j < 4; j++) {
            int d = wm + i * 16 + lrow;
            int e = wn + j * 8 + (lane & 3) * 2;
            *(float2*)&dst[d * 64 + e]       = make_float2(acc[i][j][0], acc[i][j][1]);
            *(float2*)&dst[(d + 8) * 64 + e] = make_float2(acc[i][j][2], acc[i][j][3]);
        }
    }
}

// ---------------- content + S (fused ctx-reduce) ----------------------------
__global__ __launch_bounds__(256)
void k_content() {
    int n = blockIdx.y;
    int t = blockIdx.x * 256 + threadIdx.x;
    int b = n >> 3, h = n & 7;
    const float* Q = g_qkv + ((long)b * 1536 + h * 64) * Tt;

    __shared__ float cs[4096];
    {
        const float4* p0 = (const float4*)(g_ctxp + (long)n * 4096);
        const float4* p1 = (const float4*)(g_ctxp + (long)(NHn + n) * 4096);
        const float4* p2 = (const float4*)(g_ctxp + (long)(2 * NHn + n) * 4096);
        const float4* p3 = (const float4*)(g_ctxp + (long)(3 * NHn + n) * 4096);
        for (int i = threadIdx.x; i < 1024; i += 256) {
            float4 a = p0[i], b1 = p1[i], c = p2[i], d = p3[i];
            a.x += b1.x + c.x + d.x; a.y += b1.y + c.y + d.y;
            a.z += b1.z + c.z + d.z; a.w += b1.w + c.w + d.w;
            ((float4*)cs)[i] = a;
        }
    }
    __syncthreads();

    float q[64];
    float S = 0.f;
    #pragma unroll
    for (int d = 0; d < 64; d++) {
        q[d] = Q[(long)d * Tt + t];
        S += q[d] * g_P[d * Tt + t];
    }
    g_S[n * Tt + t] = S;

    float* dst = g_mid + ((long)b * 512 + h * 64) * Tt + t;
    #pragma unroll
    for (int e0 = 0; e0 < 64; e0 += 4) {
        float4 a = make_float4(0.f, 0.f, 0.f, 0.f);
        #pragma unroll
        for (int d = 0; d < 64; d++) {
            float4 c = *(const float4*)&cs[d * 64 + e0];
            a.x += c.x * q[d]; a.y += c.y * q[d];
            a.z += c.z * q[d]; a.w += c.w * q[d];
        }
        dst[(long)(e0 + 0) * Tt] = a.x;
        dst[(long)(e0 + 1) * Tt] = a.y;
        dst[(long)(e0 + 2) * Tt] = a.z;
        dst[(long)(e0 + 3) * Tt] = a.w;
    }
}

// ---------------- BN stats ---------------------------------------------------
__global__ void k_bnstats() {
    int n = blockIdx.y, e = blockIdx.x;
    int b = n >> 3, h = n & 7;
    const float* V  = g_qkv + ((long)b * 1536 + 1024 + h * 64 + e) * Tt;
    const float* Sp = g_S + (long)n * Tt;
    int tid = threadIdx.x;
    float4 v = ((const float4*)V)[tid];
    float4 s = ((const float4*)Sp)[tid];
    float r0 = v.x * s.x, r1 = v.y * s.y, r2 = v.z * s.z, r3 = v.w * s.w;
    float sum = r0 + r1 + r2 + r3;
    float sq  = r0 * r0 + r1 * r1 + r2 * r2 + r3 * r3;
    #pragma unroll
    for (int o = 16; o; o >>= 1) {
        sum += __shfl_xor_sync(0xffffffffu, sum, o);
        sq  += __shfl_xor_sync(0xffffffffu, sq,  o);
    }
    __shared__ float ws[8], wq[8];
    if ((tid & 31) == 0) { ws[tid >> 5] = sum; wq[tid >> 5] = sq; }
    __syncthreads();
    if (tid == 0) {
        float S = 0.f, Q = 0.f;
        #pragma unroll
        for (int i = 0; i < 8; i++) { S += ws[i]; Q += wq[i]; }
        g_bns[e * 64 + n] = S;
        g_bnq[e * 64 + n] = Q;
    }
}

__global__ void k_bnred(const float* __restrict__ gamma, const float* __restrict__ beta) {
    int e = threadIdx.x;
    float s = 0.f, q = 0.f;
    #pragma unroll
    for (int n = 0; n < 64; n++) { s += g_bns[e * 64 + n]; q += g_bnq[e * 64 + n]; }
    const float cnt = (float)(NHn * Tt);
    float mu  = s / cnt;
    float var = q / cnt - mu * mu;
    float sc  = gamma[e] * rsqrtf(var + EPSf);
    g_sc[e] = sc;
    g_sh[e] = beta[e] - mu * sc;
}

// ---------------- midh = half(mid + BN(v*S)) ---------------------------------
__global__ void k_reladd() {
    int row = blockIdx.x;                 // n*64 + e == b*512 + h*64 + e
    int e = row & 63;
    int n = row >> 6;
    int b = n >> 3, h = n & 7;
    const float* V  = g_qkv + ((long)b * 1536 + 1024 + h * 64 + e) * Tt;
    const float* Sp = g_S + (long)n * Tt;
    const float* D  = g_mid + (long)row * Tt;
    __half*      Dh = g_midh + (long)row * Tt;
    float sc = g_sc[e], sh = g_sh[e];
    int tid = threadIdx.x;
    float4 v = ((const float4*)V)[tid];
    float4 s = ((const float4*)Sp)[tid];
    float4 m = ((const float4*)D)[tid];
    m.x += v.x * s.x * sc + sh;
    m.y += v.y * s.y * sc + sh;
    m.z += v.z * s.z * sc + sh;
    m.w += v.w * s.w * sc + sh;
    __half2 h0 = __floats2half2_rn(m.x, m.y);
    __half2 h1 = __floats2half2_rn(m.z, m.w);
    uint2 u;
    u.x = *(const uint32_t*)&h0;
    u.y = *(const uint32_t*)&h1;
    ((uint2*)Dh)[tid] = u;
}

// ---------------- launcher ---------------------------------------------------
extern "C" void kernel_launch(void* const* d_in, const int* in_sizes, int n_in,
                              void* d_out, int out_size) {
    const float* x      = (const float*)d_in[0];
    const float* Wqkv   = (const float*)d_in[1];
    const float* Wout   = (const float*)d_in[2];
    const float* bout   = (const float*)d_in[3];
    const float* relpos = (const float*)d_in[4];
    const float* gamma  = (const float*)d_in[5];
    const float* beta   = (const float*)d_in[6];
    float* out = (float*)d_out;

    k_prep<<<256, 256>>>(relpos);
    k_round<<<5120, 256>>>(Wqkv, x, Wout);
    k_gemm_qkv_h<<<dim3(8, 12, 8), 128>>>();
    k_mz<<<64, 256>>>();
    k_ctx_mma<<<dim3(4, 64), 128>>>();
    k_content<<<dim3(4, 64), 256>>>();
    k_bnstats<<<dim3(64, 64), 256>>>();
    k_bnred<<<1, 64>>>(gamma, beta);
    k_reladd<<<4096, 256>>>();
    k_gemm_out_h<<<dim3(8, 4, 8), 128>>>(bout, out);
}